// round 10
// baseline (speedup 1.0000x reference)
#include <cuda_runtime.h>
#include <cuda_fp16.h>
#include <cstdint>
#include <cstddef>

// ---------------- static device scratch (no runtime allocs) ----------------
__device__ float  g_h[2][50000 * 32];
__device__ float  g_agg1[50000 * 32];
__device__ float  g_agg2[50000 * 32];
__device__ float  g_inv1[50000];
__device__ float  g_inv2[50000];
__device__ int    g_cnt1[50000];
__device__ int    g_cnt2[50000];
__device__ __half g_h2i[200000 * 32];            // interior edge-MLP hidden (fp16)
__device__ __half g_h2b[40000 * 32];             // boundary edge-MLP hidden
// per-node factor matrices, one per edge type: [N][1056] = [32x32 T | 32 u]
__device__ __half g_T1[(size_t)50000 * 1056];
__device__ __half g_T2[(size_t)50000 * 1056];

__device__ __forceinline__ unsigned f2tf(float f) {
    unsigned r;
    asm("cvt.rna.tf32.f32 %0, %1;" : "=r"(r) : "f"(f));
    return r;
}

// ---------------- init: zero counts + agg, compute h0 -----------------------
__global__ void k_init(const float* __restrict__ x, const float* __restrict__ w,
                       const float* __restrict__ b, int n) {
    int i = blockIdx.x * blockDim.x + threadIdx.x;
    if (i < n * 32) {
        g_agg1[i] = 0.f;
        g_agg2[i] = 0.f;
        int nn = i >> 5, j = i & 31;
        g_h[0][i] = x[nn] * w[j] + b[j];
    }
    if (i < n) { g_cnt1[i] = 0; g_cnt2[i] = 0; }
}

__global__ void k_count(const int* __restrict__ dsti, int E,
                        const int* __restrict__ dstb, int EB) {
    int i = blockIdx.x * blockDim.x + threadIdx.x;
    if (i < E)            atomicAdd(&g_cnt1[dsti[i]], 1);
    else if (i < E + EB)  atomicAdd(&g_cnt2[dstb[i - E]], 1);
}

__global__ void k_inv(int n) {
    int i = blockIdx.x * blockDim.x + threadIdx.x;
    if (i < n) {
        g_inv1[i] = 1.f / fmaxf((float)g_cnt1[i], 1.f);
        g_inv2[i] = 1.f / fmaxf((float)g_cnt2[i], 1.f);
    }
}

// ---------------- edge-kernel MLP, first two layers (6->8->32, relu both) ---
__global__ void k_mlp(const float* __restrict__ ea, const float* __restrict__ eab,
                      const float* __restrict__ w1a, const float* __restrict__ b1a,
                      const float* __restrict__ w2a, const float* __restrict__ b2a,
                      const float* __restrict__ w1b, const float* __restrict__ b1b,
                      const float* __restrict__ w2b, const float* __restrict__ b2b,
                      int E, int EB) {
    __shared__ float sw1[2][48], sb1[2][8], sw2[2][256], sb2[2][32];
    int tid = threadIdx.x;
    for (int i = tid; i < 48;  i += blockDim.x) { sw1[0][i] = w1a[i]; sw1[1][i] = w1b[i]; }
    for (int i = tid; i < 8;   i += blockDim.x) { sb1[0][i] = b1a[i]; sb1[1][i] = b1b[i]; }
    for (int i = tid; i < 256; i += blockDim.x) { sw2[0][i] = w2a[i]; sw2[1][i] = w2b[i]; }
    for (int i = tid; i < 32;  i += blockDim.x) { sb2[0][i] = b2a[i]; sb2[1][i] = b2b[i]; }
    __syncthreads();

    int e = blockIdx.x * blockDim.x + tid;
    if (e >= E + EB) return;
    int b = (e >= E) ? 1 : 0;
    const float* a = b ? (eab + (size_t)(e - E) * 6) : (ea + (size_t)e * 6);

    float av[6];
#pragma unroll
    for (int k = 0; k < 6; k++) av[k] = a[k];

    float h1[8];
#pragma unroll
    for (int j = 0; j < 8; j++) {
        float s = sb1[b][j];
#pragma unroll
        for (int k = 0; k < 6; k++) s += av[k] * sw1[b][k * 8 + j];
        h1[j] = fmaxf(s, 0.f);
    }

    __half* o = b ? (g_h2b + (size_t)(e - E) * 32) : (g_h2i + (size_t)e * 32);
#pragma unroll
    for (int j0 = 0; j0 < 32; j0 += 4) {
        float t[4];
#pragma unroll
        for (int u = 0; u < 4; u++) {
            float s = sb2[b][j0 + u];
#pragma unroll
            for (int k = 0; k < 8; k++) s += h1[k] * sw2[b][k * 32 + j0 + u];
            t[u] = fmaxf(s, 0.f);
        }
        *(__half2*)(o + j0)     = __floats2half2_rn(t[0], t[1]);
        *(__half2*)(o + j0 + 2) = __floats2half2_rn(t[2], t[3]);
    }
}

// ---------------- per-layer T factor GEMM -----------------------------------
// T_n[k,o] = sum_i h_n[i] * w3[k, i*32+o]  (cols 0..1023, col = k*32+o)
// u_n[o]   = sum_i h_n[i] * b3[i*32+o]     (cols 1024..1055)
// tf32 mma m16n8k8; CTA tile 128 rows. One launch covers both edge types
// (same A = node features, different B = w3/b3).
#define GEMMT_SMEM (32 * 136 * 4 + 128 * 136 * 2)

__global__ void __launch_bounds__(256) k_gemmT(const float* __restrict__ w3i,
                                               const float* __restrict__ b3i,
                                               const float* __restrict__ w3b,
                                               const float* __restrict__ b3b,
                                               int Nn, int ctaN, int cur) {
    extern __shared__ float sm[];
    unsigned* bh   = (unsigned*)sm;           // [32][136] tf32 B stage
    __half*   dstg = (__half*)(sm + 32 * 136); // [128][136] output stage

    int bnd = blockIdx.x >= ctaN;
    int cta = bnd ? blockIdx.x - ctaN : blockIdx.x;
    const float* w3   = bnd ? w3b  : w3i;
    const float* b3   = bnd ? b3b  : b3i;
    __half*      Tout = bnd ? g_T2 : g_T1;
    const float* A    = g_h[cur];

    int tid = threadIdx.x;
    int wid = tid >> 5, lane = tid & 31, g = lane >> 2, t = lane & 3;
    int r0 = cta * 128 + wid * 16;
    int ra = min(r0 + g, Nn - 1);
    int rb = min(r0 + g + 8, Nn - 1);

    unsigned ah[4][4];
#pragma unroll
    for (int kk = 0; kk < 4; kk++) {
        ah[kk][0] = f2tf(A[(size_t)ra * 32 + kk * 8 + t]);
        ah[kk][1] = f2tf(A[(size_t)rb * 32 + kk * 8 + t]);
        ah[kk][2] = f2tf(A[(size_t)ra * 32 + kk * 8 + t + 4]);
        ah[kk][3] = f2tf(A[(size_t)rb * 32 + kk * 8 + t + 4]);
    }

    // ---- main 1024 columns (from permuted w3) ----
    for (int cb = 0; cb < 1024; cb += 128) {
        for (int idx = tid; idx < 32 * 128; idx += 256) {
            int i = idx >> 7, c = idx & 127;
            int col = cb + c;
            bh[i * 136 + c] = f2tf(w3[(size_t)(col >> 5) * 1024 + i * 32 + (col & 31)]);
        }
        __syncthreads();

#pragma unroll 1
        for (int nt = 0; nt < 16; nt++) {
            int n0 = nt * 8;
            float d0 = 0.f, d1 = 0.f, d2 = 0.f, d3 = 0.f;
#pragma unroll
            for (int kk = 0; kk < 4; kk++) {
                unsigned bh0 = bh[(kk * 8 + t) * 136 + n0 + g];
                unsigned bh1 = bh[(kk * 8 + t + 4) * 136 + n0 + g];
                asm volatile("mma.sync.aligned.m16n8k8.row.col.f32.tf32.tf32.f32 "
                    "{%0,%1,%2,%3}, {%4,%5,%6,%7}, {%8,%9}, {%0,%1,%2,%3};"
                    : "+f"(d0), "+f"(d1), "+f"(d2), "+f"(d3)
                    : "r"(ah[kk][0]), "r"(ah[kk][1]), "r"(ah[kk][2]), "r"(ah[kk][3]),
                      "r"(bh0), "r"(bh1));
            }
            *(__half2*)&dstg[(wid * 16 + g) * 136 + n0 + 2 * t]     = __floats2half2_rn(d0, d1);
            *(__half2*)&dstg[(wid * 16 + g + 8) * 136 + n0 + 2 * t] = __floats2half2_rn(d2, d3);
        }
        __syncthreads();
#pragma unroll
        for (int k = 0; k < 8; k++) {
            int idx = k * 256 + tid;
            int row = idx >> 4, cs = idx & 15;
            long er = (long)cta * 128 + row;
            if (er < Nn)
                *(uint4*)(Tout + (size_t)er * 1056 + cb + cs * 8) =
                    *(const uint4*)(dstg + row * 136 + cs * 8);
        }
        __syncthreads();
    }

    // ---- bias columns 1024..1055 (from b3) ----
    for (int idx = tid; idx < 32 * 32; idx += 256) {
        int i = idx >> 5, o = idx & 31;
        bh[i * 136 + o] = f2tf(b3[i * 32 + o]);
    }
    __syncthreads();
#pragma unroll
    for (int nt = 0; nt < 4; nt++) {
        int n0 = nt * 8;
        float d0 = 0.f, d1 = 0.f, d2 = 0.f, d3 = 0.f;
#pragma unroll
        for (int kk = 0; kk < 4; kk++) {
            unsigned bh0 = bh[(kk * 8 + t) * 136 + n0 + g];
            unsigned bh1 = bh[(kk * 8 + t + 4) * 136 + n0 + g];
            asm volatile("mma.sync.aligned.m16n8k8.row.col.f32.tf32.tf32.f32 "
                "{%0,%1,%2,%3}, {%4,%5,%6,%7}, {%8,%9}, {%0,%1,%2,%3};"
                : "+f"(d0), "+f"(d1), "+f"(d2), "+f"(d3)
                : "r"(ah[kk][0]), "r"(ah[kk][1]), "r"(ah[kk][2]), "r"(ah[kk][3]),
                  "r"(bh0), "r"(bh1));
        }
        *(__half2*)&dstg[(wid * 16 + g) * 136 + n0 + 2 * t]     = __floats2half2_rn(d0, d1);
        *(__half2*)&dstg[(wid * 16 + g + 8) * 136 + n0 + 2 * t] = __floats2half2_rn(d2, d3);
    }
    __syncthreads();
#pragma unroll
    for (int k = 0; k < 2; k++) {
        int idx = k * 256 + tid;
        int row = idx >> 2, cs = idx & 3;
        long er = (long)cta * 128 + row;
        if (er < Nn)
            *(uint4*)(Tout + (size_t)er * 1056 + 1024 + cs * 8) =
                *(const uint4*)(dstg + row * 136 + cs * 8);
    }
}

// ---------------- per-layer edge scatter (warp per edge, merged) ------------
// msg_e[o] = sum_k h2_e[k] * T_src[k,o] + u_src[o];  one atomic per lane.
__global__ void k_scatter(const int* __restrict__ ei, const int* __restrict__ eib,
                          int E, int EB) {
    int w    = (blockIdx.x * blockDim.x + threadIdx.x) >> 5;
    int lane = threadIdx.x & 31;
    if (w >= E + EB) return;

    int bnd = w >= E;
    int e   = bnd ? w - E : w;
    const int*    src = bnd ? eib      : ei;
    const int*    dst = bnd ? eib + EB : ei + E;
    const __half* h2  = bnd ? g_h2b    : g_h2i;
    const __half* T   = bnd ? g_T2     : g_T1;
    float*        agg = bnd ? g_agg2   : g_agg1;

    int s = __ldg(src + e);
    int d = __ldg(dst + e);
    float hv = __half2float(__ldg(h2 + (size_t)e * 32 + lane));

    const __half* Ts = T + (size_t)s * 1056;
    const uint4*  Tr = (const uint4*)Ts;
    int g = lane >> 2, c = lane & 3;

    float acc[8];
#pragma unroll
    for (int t = 0; t < 8; t++) acc[t] = 0.f;

#pragma unroll
    for (int j = 0; j < 4; j++) {
        uint4 wv = __ldg(Tr + j * 32 + lane);    // T[8j+g][8c .. 8c+8)
        float xi = __shfl_sync(0xffffffffu, hv, 8 * j + g);
        __half2* hp = (__half2*)&wv;
#pragma unroll
        for (int q = 0; q < 4; q++) {
            float2 f = __half22float2(hp[q]);
            acc[2 * q]     += xi * f.x;
            acc[2 * q + 1] += xi * f.y;
        }
    }
#pragma unroll
    for (int m = 4; m < 32; m <<= 1)
#pragma unroll
        for (int t = 0; t < 8; t++)
            acc[t] += __shfl_xor_sync(0xffffffffu, acc[t], m);

    float val = acc[0];
#pragma unroll
    for (int t = 1; t < 8; t++) val = (g == t) ? acc[t] : val;
    // per-edge bias term u_src[8c+g]
    val += __half2float(__ldg(Ts + 1024 + 8 * c + g));
    atomicAdd(agg + (size_t)d * 32 + 8 * c + g, val);
}

// ---------------- node update: relu(mean1+mean2 + h@(r1+r2) + b1+b2) --------
// also re-zeros agg buffers for the next layer.
__global__ void k_update(const float* __restrict__ r1, const float* __restrict__ b1,
                         const float* __restrict__ r2, const float* __restrict__ b2,
                         int n, int cur) {
    __shared__ float rs[1024];
    __shared__ float bs[32];
    int tid = threadIdx.x;
    for (int k = tid; k < 1024; k += blockDim.x) rs[k] = r1[k] + r2[k];
    if (tid < 32) bs[tid] = b1[tid] + b2[tid];
    __syncthreads();

    int w = (blockIdx.x * blockDim.x + tid) >> 5;
    int lane = tid & 31;
    if (w >= n) return;

    const float* h  = g_h[cur];
    float*       hn = g_h[cur ^ 1];
    size_t idx = (size_t)w * 32 + lane;

    float xv  = h[idx];
    float acc = g_agg1[idx] * g_inv1[w] + g_agg2[idx] * g_inv2[w] + bs[lane];
    g_agg1[idx] = 0.f;
    g_agg2[idx] = 0.f;
#pragma unroll
    for (int i = 0; i < 32; i++)
        acc += __shfl_sync(0xffffffffu, xv, i) * rs[i * 32 + lane];
    hn[idx] = fmaxf(acc, 0.f);
}

__global__ void k_final(const float* __restrict__ fc2w, const float* __restrict__ fc2b,
                        float* __restrict__ out, int n, int cur) {
    int w = (blockIdx.x * blockDim.x + threadIdx.x) >> 5;
    int lane = threadIdx.x & 31;
    if (w >= n) return;
    float v = g_h[cur][(size_t)w * 32 + lane] * fc2w[lane];
#pragma unroll
    for (int m = 16; m; m >>= 1) v += __shfl_xor_sync(0xffffffffu, v, m);
    if (lane == 0) out[w] = v + fc2b[0];
}

// ---------------- launcher --------------------------------------------------
extern "C" void kernel_launch(void* const* d_in, const int* in_sizes, int n_in,
                              void* d_out, int out_size) {
    const float* x    = (const float*)d_in[0];
    const int*   ei   = (const int*)d_in[1];
    const float* ea   = (const float*)d_in[2];
    const int*   eib  = (const int*)d_in[3];
    const float* eab  = (const float*)d_in[4];
    const float* fc1w = (const float*)d_in[5];
    const float* fc1b = (const float*)d_in[6];
    const float* k1w1 = (const float*)d_in[7],  *k1b1 = (const float*)d_in[8];
    const float* k1w2 = (const float*)d_in[9],  *k1b2 = (const float*)d_in[10];
    const float* k1w3 = (const float*)d_in[11], *k1b3 = (const float*)d_in[12];
    const float* k2w1 = (const float*)d_in[13], *k2b1 = (const float*)d_in[14];
    const float* k2w2 = (const float*)d_in[15], *k2b2 = (const float*)d_in[16];
    const float* k2w3 = (const float*)d_in[17], *k2b3 = (const float*)d_in[18];
    const float* r1   = (const float*)d_in[19], *b1   = (const float*)d_in[20];
    const float* r2   = (const float*)d_in[21], *b2   = (const float*)d_in[22];
    const float* fc2w = (const float*)d_in[23], *fc2b = (const float*)d_in[24];
    float* out = (float*)d_out;

    int N  = in_sizes[0];
    int E  = in_sizes[1] / 2;
    int EB = in_sizes[3] / 2;

    cudaFuncSetAttribute(k_gemmT, cudaFuncAttributeMaxDynamicSharedMemorySize, GEMMT_SMEM);

    k_init<<<(N * 32 + 255) / 256, 256>>>(x, fc1w, fc1b, N);
    k_count<<<(E + EB + 255) / 256, 256>>>(ei + E, E, eib + EB, EB);
    k_inv<<<(N + 255) / 256, 256>>>(N);
    k_mlp<<<(E + EB + 255) / 256, 256>>>(ea, eab, k1w1, k1b1, k1w2, k1b2,
                                         k2w1, k2b1, k2w2, k2b2, E, EB);

    int ctaN = (N + 127) / 128;
    int cur = 0;
    for (int l = 0; l < 4; l++) {
        k_gemmT<<<2 * ctaN, 256, GEMMT_SMEM>>>(k1w3, k1b3, k2w3, k2b3, N, ctaN, cur);
        k_scatter<<<((E + EB) * 32 + 255) / 256, 256>>>(ei, eib, E, EB);
        k_update<<<(N * 32 + 255) / 256, 256>>>(r1, b1, r2, b2, N, cur);
        cur ^= 1;
    }
    k_final<<<(N * 32 + 255) / 256, 256>>>(fc2w, fc2b, out, N, cur);
}

// round 11
// speedup vs baseline: 1.4298x; 1.4298x over previous
#include <cuda_runtime.h>
#include <cuda_fp16.h>
#include <cstdint>
#include <cstddef>

// ---------------- static device scratch (no runtime allocs) ----------------
__device__ float  g_h[2][50000 * 32];
__device__ float  g_agg1[50000 * 32];
__device__ float  g_agg2[50000 * 32];
__device__ float  g_inv1[50000];
__device__ float  g_inv2[50000];
__device__ int    g_cnt1[50000];
__device__ int    g_cnt2[50000];
__device__ float  g_h2i[200000 * 32];            // interior edge-MLP hidden (post relu)
__device__ float  g_h2b[40000 * 32];             // boundary edge-MLP hidden
__device__ __half g_W1[(size_t)200000 * 1024];   // per-edge [32x32] matrices, fp16
__device__ __half g_W2[(size_t)40000 * 1024];

__device__ __forceinline__ unsigned f2tf(float f) {
    unsigned r;
    asm("cvt.rna.tf32.f32 %0, %1;" : "=r"(r) : "f"(f));
    return r;
}

// ---------------- init: zero counts + agg, compute h0 -----------------------
__global__ void k_init(const float* __restrict__ x, const float* __restrict__ w,
                       const float* __restrict__ b, int n) {
    int i = blockIdx.x * blockDim.x + threadIdx.x;
    if (i < n * 32) {
        g_agg1[i] = 0.f;
        g_agg2[i] = 0.f;
        int nn = i >> 5, j = i & 31;
        g_h[0][i] = x[nn] * w[j] + b[j];
    }
    if (i < n) { g_cnt1[i] = 0; g_cnt2[i] = 0; }
}

__global__ void k_count(const int* __restrict__ dsti, int E,
                        const int* __restrict__ dstb, int EB) {
    int i = blockIdx.x * blockDim.x + threadIdx.x;
    if (i < E)            atomicAdd(&g_cnt1[dsti[i]], 1);
    else if (i < E + EB)  atomicAdd(&g_cnt2[dstb[i - E]], 1);
}

__global__ void k_inv(int n) {
    int i = blockIdx.x * blockDim.x + threadIdx.x;
    if (i < n) {
        g_inv1[i] = 1.f / fmaxf((float)g_cnt1[i], 1.f);
        g_inv2[i] = 1.f / fmaxf((float)g_cnt2[i], 1.f);
    }
}

// ---------------- edge-kernel MLP, first two layers (6->8->32, relu both) ---
__global__ void k_mlp(const float* __restrict__ ea, const float* __restrict__ eab,
                      const float* __restrict__ w1a, const float* __restrict__ b1a,
                      const float* __restrict__ w2a, const float* __restrict__ b2a,
                      const float* __restrict__ w1b, const float* __restrict__ b1b,
                      const float* __restrict__ w2b, const float* __restrict__ b2b,
                      int E, int EB) {
    __shared__ float sw1[2][48], sb1[2][8], sw2[2][256], sb2[2][32];
    int tid = threadIdx.x;
    for (int i = tid; i < 48;  i += blockDim.x) { sw1[0][i] = w1a[i]; sw1[1][i] = w1b[i]; }
    for (int i = tid; i < 8;   i += blockDim.x) { sb1[0][i] = b1a[i]; sb1[1][i] = b1b[i]; }
    for (int i = tid; i < 256; i += blockDim.x) { sw2[0][i] = w2a[i]; sw2[1][i] = w2b[i]; }
    for (int i = tid; i < 32;  i += blockDim.x) { sb2[0][i] = b2a[i]; sb2[1][i] = b2b[i]; }
    __syncthreads();

    int e = blockIdx.x * blockDim.x + tid;
    if (e >= E + EB) return;
    int b = (e >= E) ? 1 : 0;
    const float* a = b ? (eab + (size_t)(e - E) * 6) : (ea + (size_t)e * 6);

    float av[6];
#pragma unroll
    for (int k = 0; k < 6; k++) av[k] = a[k];

    float h1[8];
#pragma unroll
    for (int j = 0; j < 8; j++) {
        float s = sb1[b][j];
#pragma unroll
        for (int k = 0; k < 6; k++) s += av[k] * sw1[b][k * 8 + j];
        h1[j] = fmaxf(s, 0.f);
    }

    float* o = b ? (g_h2b + (size_t)(e - E) * 32) : (g_h2i + (size_t)e * 32);
#pragma unroll
    for (int j0 = 0; j0 < 32; j0 += 4) {
        float t[4];
#pragma unroll
        for (int u = 0; u < 4; u++) {
            float s = sb2[b][j0 + u];
#pragma unroll
            for (int k = 0; k < 8; k++) s += h1[k] * sw2[b][k * 32 + j0 + u];
            t[u] = fmaxf(s, 0.f);
        }
        *(float4*)(o + j0) = make_float4(t[0], t[1], t[2], t[3]);
    }
}

// ---------------- W materialization: C[M,1024] = A[M,32] @ w3 + b3 ----------
// Single-pass tf32 mma m16n8k8. One launch covers interior + boundary;
// CTA tile = 128 rows x 128-col chunks; B chunk + b3 staged in smem,
// output staged in smem for coalesced STG.128.
#define GEMM_SMEM (32 * 136 * 4 + 1024 * 4 + 128 * 136 * 2)

__global__ void __launch_bounds__(256) k_gemm(const float* __restrict__ w3i,
                                              const float* __restrict__ b3i,
                                              const float* __restrict__ w3b,
                                              const float* __restrict__ b3b,
                                              int E, int EB, int ctaI) {
    extern __shared__ float sm[];
    unsigned* bh   = (unsigned*)sm;                 // [32][136] tf32
    float*    b3s  = sm + 32 * 136;                 // [1024]
    __half*   dstg = (__half*)(sm + 32 * 136 + 1024); // [128][136] output stage

    int bnd = blockIdx.x >= ctaI;
    int cta = bnd ? blockIdx.x - ctaI : blockIdx.x;
    int M   = bnd ? EB : E;
    const float* w3   = bnd ? w3b   : w3i;
    const float* b3   = bnd ? b3b   : b3i;
    const float* A    = bnd ? g_h2b : g_h2i;
    __half*      Wout = bnd ? g_W2  : g_W1;

    int tid = threadIdx.x;
    int wid = tid >> 5, lane = tid & 31, g = lane >> 2, t = lane & 3;
    int e0 = cta * 128 + wid * 16;
    int ra = min(e0 + g, M - 1);
    int rb = min(e0 + g + 8, M - 1);

    for (int idx = tid; idx < 1024; idx += 256) b3s[idx] = b3[idx];

    unsigned ah[4][4];
#pragma unroll
    for (int kk = 0; kk < 4; kk++) {
        ah[kk][0] = f2tf(A[(size_t)ra * 32 + kk * 8 + t]);
        ah[kk][1] = f2tf(A[(size_t)rb * 32 + kk * 8 + t]);
        ah[kk][2] = f2tf(A[(size_t)ra * 32 + kk * 8 + t + 4]);
        ah[kk][3] = f2tf(A[(size_t)rb * 32 + kk * 8 + t + 4]);
    }

    for (int cb = 0; cb < 1024; cb += 128) {
        // stage B chunk [32 x 128] as tf32
        for (int idx = tid; idx < 32 * 128; idx += 256) {
            int r = idx >> 7, c = idx & 127;
            bh[r * 136 + c] = f2tf(w3[(size_t)r * 1024 + cb + c]);
        }
        __syncthreads();

#pragma unroll 2
        for (int nt = 0; nt < 16; nt++) {
            int n0 = nt * 8;
            float d0 = b3s[cb + n0 + 2 * t];
            float d1 = b3s[cb + n0 + 2 * t + 1];
            float d2 = d0, d3 = d1;
#pragma unroll
            for (int kk = 0; kk < 4; kk++) {
                unsigned bh0 = bh[(kk * 8 + t) * 136 + n0 + g];
                unsigned bh1 = bh[(kk * 8 + t + 4) * 136 + n0 + g];
                asm volatile("mma.sync.aligned.m16n8k8.row.col.f32.tf32.tf32.f32 "
                    "{%0,%1,%2,%3}, {%4,%5,%6,%7}, {%8,%9}, {%0,%1,%2,%3};"
                    : "+f"(d0), "+f"(d1), "+f"(d2), "+f"(d3)
                    : "r"(ah[kk][0]), "r"(ah[kk][1]), "r"(ah[kk][2]), "r"(ah[kk][3]),
                      "r"(bh0), "r"(bh1));
            }
            *(__half2*)&dstg[(wid * 16 + g) * 136 + n0 + 2 * t]     = __floats2half2_rn(d0, d1);
            *(__half2*)&dstg[(wid * 16 + g + 8) * 136 + n0 + 2 * t] = __floats2half2_rn(d2, d3);
        }
        __syncthreads();
        // coalesced write-out: 2048 uint4 = 128 rows x 128 cols of halves
#pragma unroll
        for (int k = 0; k < 8; k++) {
            int idx = k * 256 + tid;
            int row = idx >> 4, cs = idx & 15;
            long er = (long)cta * 128 + row;
            if (er < M)
                *(uint4*)(Wout + (size_t)er * 1024 + cb + cs * 8) =
                    *(const uint4*)(dstg + row * 136 + cs * 8);
        }
        __syncthreads();
    }
}

// ---------------- per-layer edge scatter (warp per 2 edges, merged) ---------
// W stream read with __ldcs (evict-first). 2 edges/warp doubles front-batched
// LDG.128 MLP (4 -> 8) to hide DRAM latency at moderate occupancy.
__global__ void k_scatter(const int* __restrict__ ei, const int* __restrict__ eib,
                          int E, int EB, int cur) {
    int w    = (blockIdx.x * blockDim.x + threadIdx.x) >> 5;
    int lane = threadIdx.x & 31;
    int ET   = E + EB;
    int e0   = 2 * w;
    if (e0 >= ET) return;
    int g = lane >> 2, c = lane & 3;
    const float* h = g_h[cur];

    // ---- edge 0 descriptors + loads ----
    int bnd0 = e0 >= E;
    int a0   = bnd0 ? e0 - E : e0;
    int s0   = __ldg((bnd0 ? eib : ei) + a0);
    int d0   = __ldg((bnd0 ? eib + EB : ei + E) + a0);
    const uint4* Wr0 = (const uint4*)((bnd0 ? g_W2 : g_W1) + (size_t)a0 * 1024);
    float xv0 = h[(size_t)s0 * 32 + lane];

    // ---- edge 1 descriptors + loads (may be absent) ----
    int e1 = e0 + 1;
    bool has1 = e1 < ET;
    int bnd1 = e1 >= E;
    int a1   = bnd1 ? e1 - E : e1;
    if (!has1) { bnd1 = bnd0; a1 = a0; }
    int s1   = __ldg((bnd1 ? eib : ei) + a1);
    int d1   = __ldg((bnd1 ? eib + EB : ei + E) + a1);
    const uint4* Wr1 = (const uint4*)((bnd1 ? g_W2 : g_W1) + (size_t)a1 * 1024);
    float xv1 = h[(size_t)s1 * 32 + lane];

    uint4 wv0[4], wv1[4];
#pragma unroll
    for (int j = 0; j < 4; j++) wv0[j] = __ldcs(Wr0 + j * 32 + lane);
#pragma unroll
    for (int j = 0; j < 4; j++) wv1[j] = __ldcs(Wr1 + j * 32 + lane);

    float acc0[8], acc1[8];
#pragma unroll
    for (int t = 0; t < 8; t++) { acc0[t] = 0.f; acc1[t] = 0.f; }

#pragma unroll
    for (int j = 0; j < 4; j++) {
        float xi0 = __shfl_sync(0xffffffffu, xv0, 8 * j + g);
        float xi1 = __shfl_sync(0xffffffffu, xv1, 8 * j + g);
        __half2* hp0 = (__half2*)&wv0[j];
        __half2* hp1 = (__half2*)&wv1[j];
#pragma unroll
        for (int q = 0; q < 4; q++) {
            float2 f0 = __half22float2(hp0[q]);
            float2 f1 = __half22float2(hp1[q]);
            acc0[2 * q]     += xi0 * f0.x;
            acc0[2 * q + 1] += xi0 * f0.y;
            acc1[2 * q]     += xi1 * f1.x;
            acc1[2 * q + 1] += xi1 * f1.y;
        }
    }
#pragma unroll
    for (int m = 4; m < 32; m <<= 1)
#pragma unroll
        for (int t = 0; t < 8; t++) {
            acc0[t] += __shfl_xor_sync(0xffffffffu, acc0[t], m);
            acc1[t] += __shfl_xor_sync(0xffffffffu, acc1[t], m);
        }

    float val0 = acc0[0], val1 = acc1[0];
#pragma unroll
    for (int t = 1; t < 8; t++) {
        val0 = (g == t) ? acc0[t] : val0;
        val1 = (g == t) ? acc1[t] : val1;
    }
    atomicAdd((bnd0 ? g_agg2 : g_agg1) + (size_t)d0 * 32 + 8 * c + g, val0);
    if (has1)
        atomicAdd((bnd1 ? g_agg2 : g_agg1) + (size_t)d1 * 32 + 8 * c + g, val1);
}

// ---------------- node update: relu(mean1+mean2 + h@(r1+r2) + b1+b2) --------
// also re-zeros agg buffers for the next layer.
__global__ void k_update(const float* __restrict__ r1, const float* __restrict__ b1,
                         const float* __restrict__ r2, const float* __restrict__ b2,
                         int n, int cur) {
    __shared__ float rs[1024];
    __shared__ float bs[32];
    int tid = threadIdx.x;
    for (int k = tid; k < 1024; k += blockDim.x) rs[k] = r1[k] + r2[k];
    if (tid < 32) bs[tid] = b1[tid] + b2[tid];
    __syncthreads();

    int w = (blockIdx.x * blockDim.x + tid) >> 5;
    int lane = tid & 31;
    if (w >= n) return;

    const float* h  = g_h[cur];
    float*       hn = g_h[cur ^ 1];
    size_t idx = (size_t)w * 32 + lane;

    float xv  = h[idx];
    float acc = g_agg1[idx] * g_inv1[w] + g_agg2[idx] * g_inv2[w] + bs[lane];
    g_agg1[idx] = 0.f;
    g_agg2[idx] = 0.f;
#pragma unroll
    for (int i = 0; i < 32; i++)
        acc += __shfl_sync(0xffffffffu, xv, i) * rs[i * 32 + lane];
    hn[idx] = fmaxf(acc, 0.f);
}

__global__ void k_final(const float* __restrict__ fc2w, const float* __restrict__ fc2b,
                        float* __restrict__ out, int n, int cur) {
    int w = (blockIdx.x * blockDim.x + threadIdx.x) >> 5;
    int lane = threadIdx.x & 31;
    if (w >= n) return;
    float v = g_h[cur][(size_t)w * 32 + lane] * fc2w[lane];
#pragma unroll
    for (int m = 16; m; m >>= 1) v += __shfl_xor_sync(0xffffffffu, v, m);
    if (lane == 0) out[w] = v + fc2b[0];
}

// ---------------- launcher --------------------------------------------------
extern "C" void kernel_launch(void* const* d_in, const int* in_sizes, int n_in,
                              void* d_out, int out_size) {
    const float* x    = (const float*)d_in[0];
    const int*   ei   = (const int*)d_in[1];
    const float* ea   = (const float*)d_in[2];
    const int*   eib  = (const int*)d_in[3];
    const float* eab  = (const float*)d_in[4];
    const float* fc1w = (const float*)d_in[5];
    const float* fc1b = (const float*)d_in[6];
    const float* k1w1 = (const float*)d_in[7],  *k1b1 = (const float*)d_in[8];
    const float* k1w2 = (const float*)d_in[9],  *k1b2 = (const float*)d_in[10];
    const float* k1w3 = (const float*)d_in[11], *k1b3 = (const float*)d_in[12];
    const float* k2w1 = (const float*)d_in[13], *k2b1 = (const float*)d_in[14];
    const float* k2w2 = (const float*)d_in[15], *k2b2 = (const float*)d_in[16];
    const float* k2w3 = (const float*)d_in[17], *k2b3 = (const float*)d_in[18];
    const float* r1   = (const float*)d_in[19], *b1   = (const float*)d_in[20];
    const float* r2   = (const float*)d_in[21], *b2   = (const float*)d_in[22];
    const float* fc2w = (const float*)d_in[23], *fc2b = (const float*)d_in[24];
    float* out = (float*)d_out;

    int N  = in_sizes[0];
    int E  = in_sizes[1] / 2;
    int EB = in_sizes[3] / 2;

    cudaFuncSetAttribute(k_gemm, cudaFuncAttributeMaxDynamicSharedMemorySize, GEMM_SMEM);

    int ctaI = (E + 127) / 128, ctaB = (EB + 127) / 128;
    int scatGrid = (((E + EB + 1) / 2) * 32 + 255) / 256;

    // Order chosen so the FIRST k_scatter is launch #4 (ncu captures launch #4):
    // count/inv only feed k_update, so they can run after the first scatter.
    k_init<<<(N * 32 + 255) / 256, 256>>>(x, fc1w, fc1b, N);                     // 1
    k_mlp<<<(E + EB + 255) / 256, 256>>>(ea, eab, k1w1, k1b1, k1w2, k1b2,
                                         k2w1, k2b1, k2w2, k2b2, E, EB);         // 2
    k_gemm<<<ctaI + ctaB, 256, GEMM_SMEM>>>(k1w3, k1b3, k2w3, k2b3, E, EB, ctaI); // 3
    k_scatter<<<scatGrid, 256>>>(ei, eib, E, EB, 0);                              // 4 <- profiled
    k_count<<<(E + EB + 255) / 256, 256>>>(ei + E, E, eib + EB, EB);              // 5
    k_inv<<<(N + 255) / 256, 256>>>(N);                                           // 6
    k_update<<<(N * 32 + 255) / 256, 256>>>(r1, b1, r2, b2, N, 0);                // 7

    int cur = 1;
    for (int l = 1; l < 4; l++) {
        k_scatter<<<scatGrid, 256>>>(ei, eib, E, EB, cur);
        k_update<<<(N * 32 + 255) / 256, 256>>>(r1, b1, r2, b2, N, cur);
        cur ^= 1;
    }
    k_final<<<(N * 32 + 255) / 256, 256>>>(fc2w, fc2b, out, N, cur);
}